// round 2
// baseline (speedup 1.0000x reference)
#include <cuda_runtime.h>
#include <cuda_bf16.h>

#define BB    2048
#define DM    128
#define FF    12800
#define NDLLM 768
#define NDFF  256
#define NE    8
#define NGIN  13569          // 768 + 1 + 12800
#define GATE_SPLIT 8
#define KSEG_GATE  1697      // ceil(13569/8)
#define GEN_SPLIT  8
#define KSEG_GEN   1600      // 12800/8

// scratch (static device globals; no allocation allowed)
__device__ float g_gate_partial[(size_t)GATE_SPLIT * BB * NDFF]; // 16.8 MB
__device__ float g_gen_partial[(size_t)GEN_SPLIT * BB * DM];     // 8.4 MB
__device__ float g_combined[(size_t)BB * DM];                    // 1 MB
__device__ int   g_counts[NE];
__device__ int   g_list[NE * BB];
__device__ float g_gateval[NE * BB];

// ---------------------------------------------------------------------------
// 0) zero the accumulators that are atomically built each call
// ---------------------------------------------------------------------------
__global__ void init_zero_kernel() {
    int i = blockIdx.x * blockDim.x + threadIdx.x;
    if (i < BB * DM) g_combined[i] = 0.0f;
    if (i < NE) g_counts[i] = 0;
}

// ---------------------------------------------------------------------------
// 1) gate GEMM: partial[s][b][j] = sum_{k in seg s} gin[b][k] * Wg1[k][j]
//    gin = concat(DKP[768], cycle[1], xf[12800]) assembled on the fly.
//    BM=32 tokens, BN=256 (all of DFF), BK=32, split-K=8 -> 512 CTAs
// ---------------------------------------------------------------------------
__global__ void __launch_bounds__(256)
gate_gemm_kernel(const float* __restrict__ xf, const float* __restrict__ cyc,
                 const float* __restrict__ dkp, const float* __restrict__ Wg1) {
    __shared__ float As[32][33];    // [k][m], padded
    __shared__ float Bs[32][256];   // [k][n]
    const int bm   = blockIdx.x * 32;
    const int s    = blockIdx.y;
    const int kbeg = s * KSEG_GATE;
    const int kend = min(NGIN, kbeg + KSEG_GATE);
    const int tid  = threadIdx.x;
    const int tx   = tid & 31;      // col lane: covers cols tx + 32*j
    const int ty   = tid >> 5;      // row group: covers tokens ty*4 .. ty*4+3

    float acc[4][8];
#pragma unroll
    for (int i = 0; i < 4; i++)
#pragma unroll
        for (int j = 0; j < 8; j++) acc[i][j] = 0.0f;

    for (int k0 = kbeg; k0 < kend; k0 += 32) {
        // A tile: 32 tokens x 32 k (gathered from virtual concat)
        {
            const int kk = tid & 31;
            const int mbase = tid >> 5;
            const int k = k0 + kk;
#pragma unroll
            for (int i = 0; i < 4; i++) {
                const int mm = mbase + i * 8;
                const int b = bm + mm;
                float v = 0.0f;
                if (k < kend) {
                    if (k < NDLLM)       v = dkp[(size_t)b * NDLLM + k];
                    else if (k == NDLLM) v = cyc[b];
                    else                 v = xf[(size_t)b * FF + (k - NDLLM - 1)];
                }
                As[kk][mm] = v;
            }
        }
        // B tile: 32 x 256 via float4
        {
            const int c4 = tid & 63;        // 0..63 -> cols c4*4..c4*4+3
            const int rbase = tid >> 6;     // 0..3
#pragma unroll
            for (int p = 0; p < 8; p++) {
                const int r = rbase + p * 4;
                const int k = k0 + r;
                float4 v = make_float4(0.f, 0.f, 0.f, 0.f);
                if (k < kend)
                    v = *reinterpret_cast<const float4*>(&Wg1[(size_t)k * NDFF + c4 * 4]);
                *reinterpret_cast<float4*>(&Bs[r][c4 * 4]) = v;
            }
        }
        __syncthreads();
#pragma unroll
        for (int kk = 0; kk < 32; kk++) {
            const float a0 = As[kk][ty * 4 + 0];
            const float a1 = As[kk][ty * 4 + 1];
            const float a2 = As[kk][ty * 4 + 2];
            const float a3 = As[kk][ty * 4 + 3];
#pragma unroll
            for (int j = 0; j < 8; j++) {
                const float bv = Bs[kk][tx + 32 * j];   // bank = tx, conflict-free
                acc[0][j] += a0 * bv;
                acc[1][j] += a1 * bv;
                acc[2][j] += a2 * bv;
                acc[3][j] += a3 * bv;
            }
        }
        __syncthreads();
    }
#pragma unroll
    for (int i = 0; i < 4; i++) {
        const int t = bm + ty * 4 + i;
#pragma unroll
        for (int j = 0; j < 8; j++)
            g_gate_partial[((size_t)s * BB + t) * NDFF + tx + 32 * j] = acc[i][j];
    }
}

// ---------------------------------------------------------------------------
// 2) gate epilogue: reduce split-K partials, +bg1, gelu(tanh approx),
//    @Wg2 + bg2, softmax over all 8, top-2 (lower-index tie-break),
//    renormalize (+1e-9), build per-expert dispatch lists.
//    One warp per token.
// ---------------------------------------------------------------------------
__global__ void __launch_bounds__(256)
gate_epilogue_kernel(const float* __restrict__ bg1, const float* __restrict__ Wg2,
                     const float* __restrict__ bg2) {
    const int warp = threadIdx.x >> 5;
    const int lane = threadIdx.x & 31;
    const int t = blockIdx.x * 8 + warp;
    if (t >= BB) return;

    float h[8];
#pragma unroll
    for (int j = 0; j < 8; j++) {
        const int c = lane + 32 * j;
        float v = bg1[c];
#pragma unroll
        for (int s = 0; s < GATE_SPLIT; s++)
            v += g_gate_partial[((size_t)s * BB + t) * NDFF + c];
        // JAX default gelu: approximate=True (tanh)
        const float x = v;
        const float inner = 0.7978845608028654f * (x + 0.044715f * x * x * x);
        h[j] = 0.5f * x * (1.0f + tanhf(inner));
    }
    float le[NE];
#pragma unroll
    for (int e = 0; e < NE; e++) {
        float s = 0.0f;
#pragma unroll
        for (int j = 0; j < 8; j++)
            s += h[j] * Wg2[(size_t)(lane + 32 * j) * NE + e];
#pragma unroll
        for (int o = 16; o > 0; o >>= 1)
            s += __shfl_xor_sync(0xffffffffu, s, o);
        le[e] = s;
    }
    if (lane == 0) {
        float logits[NE];
#pragma unroll
        for (int e = 0; e < NE; e++) logits[e] = le[e] + bg2[e];
        float mx = logits[0];
#pragma unroll
        for (int e = 1; e < NE; e++) mx = fmaxf(mx, logits[e]);
        float p[NE];
        float sum = 0.0f;
#pragma unroll
        for (int e = 0; e < NE; e++) { p[e] = __expf(logits[e] - mx) ; p[e] = expf(logits[e] - mx); sum += p[e]; }
#pragma unroll
        for (int e = 0; e < NE; e++) p[e] /= sum;
        int i1 = 0;
#pragma unroll
        for (int e = 1; e < NE; e++) if (logits[e] > logits[i1]) i1 = e;
        int i2 = (i1 == 0) ? 1 : 0;
#pragma unroll
        for (int e = 0; e < NE; e++)
            if (e != i1 && logits[e] > logits[i2]) i2 = e;
        const float denom = p[i1] + p[i2] + 1e-9f;
        const float g1 = p[i1] / denom;
        const float g2 = p[i2] / denom;
        int pos1 = atomicAdd(&g_counts[i1], 1);
        g_list[i1 * BB + pos1] = t;
        g_gateval[i1 * BB + pos1] = g1;
        int pos2 = atomicAdd(&g_counts[i2], 1);
        g_list[i2 * BB + pos2] = t;
        g_gateval[i2 * BB + pos2] = g2;
    }
}

// ---------------------------------------------------------------------------
// 3) general GEMM: gen_partial[s][b][d] = sum_{k in seg} xf[b][k]*Wgen[k][d]
//    BM=32, BN=128, BK=32, split-K=8 -> 512 CTAs
// ---------------------------------------------------------------------------
__global__ void __launch_bounds__(256)
general_gemm_kernel(const float* __restrict__ xf, const float* __restrict__ Wgen) {
    __shared__ float As[32][33];
    __shared__ float Bs[32][128];
    const int bm = blockIdx.x * 32;
    const int s = blockIdx.y;
    const int kbeg = s * KSEG_GEN;
    const int kend = kbeg + KSEG_GEN;
    const int tid = threadIdx.x;
    const int tx = tid & 31;
    const int ty = tid >> 5;

    float acc[4][4];
#pragma unroll
    for (int i = 0; i < 4; i++)
#pragma unroll
        for (int j = 0; j < 4; j++) acc[i][j] = 0.0f;

    for (int k0 = kbeg; k0 < kend; k0 += 32) {
        {
            const int kk = tid & 31;
            const int mbase = tid >> 5;
#pragma unroll
            for (int i = 0; i < 4; i++) {
                const int mm = mbase + i * 8;
                As[kk][mm] = xf[(size_t)(bm + mm) * FF + k0 + kk];
            }
        }
        {
            const int c4 = tid & 31;
            const int rbase = tid >> 5;
#pragma unroll
            for (int p = 0; p < 4; p++) {
                const int r = rbase + p * 8;
                float4 v = *reinterpret_cast<const float4*>(&Wgen[(size_t)(k0 + r) * DM + c4 * 4]);
                *reinterpret_cast<float4*>(&Bs[r][c4 * 4]) = v;
            }
        }
        __syncthreads();
#pragma unroll
        for (int kk = 0; kk < 32; kk++) {
            const float a0 = As[kk][ty * 4 + 0];
            const float a1 = As[kk][ty * 4 + 1];
            const float a2 = As[kk][ty * 4 + 2];
            const float a3 = As[kk][ty * 4 + 3];
#pragma unroll
            for (int j = 0; j < 4; j++) {
                const float bv = Bs[kk][tx + 32 * j];
                acc[0][j] += a0 * bv;
                acc[1][j] += a1 * bv;
                acc[2][j] += a2 * bv;
                acc[3][j] += a3 * bv;
            }
        }
        __syncthreads();
    }
#pragma unroll
    for (int i = 0; i < 4; i++) {
        const int t = bm + ty * 4 + i;
#pragma unroll
        for (int j = 0; j < 4; j++)
            g_gen_partial[((size_t)s * BB + t) * DM + tx + 32 * j] = acc[i][j];
    }
}

// ---------------------------------------------------------------------------
// 4) expert GEMMs (gathered): for each expert e, for its token list,
//    combined[t][d] += gate * (xf[t] . We[e][:,d] + be[e][d])
//    Exactly 2 atomic contributions per (t,d): order-independent fp32 sum.
// ---------------------------------------------------------------------------
__global__ void __launch_bounds__(256)
expert_gemm_kernel(const float* __restrict__ xf, const float* __restrict__ We,
                   const float* __restrict__ be) {
    __shared__ float As[32][33];
    __shared__ float Bs[32][128];
    __shared__ int   s_tok[32];
    __shared__ float s_gate[32];
    const int e = blockIdx.y;
    const int n = g_counts[e];
    const int t0 = blockIdx.x * 32;
    if (t0 >= n) return;

    const int tid = threadIdx.x;
    if (tid < 32) {
        const int idx = t0 + tid;
        s_tok[tid]  = (idx < n) ? g_list[e * BB + idx] : -1;
        s_gate[tid] = (idx < n) ? g_gateval[e * BB + idx] : 0.0f;
    }
    __syncthreads();

    const int tx = tid & 31;
    const int ty = tid >> 5;
    const float* W = We + (size_t)e * FF * DM;

    float acc[4][4];
#pragma unroll
    for (int i = 0; i < 4; i++)
#pragma unroll
        for (int j = 0; j < 4; j++) acc[i][j] = 0.0f;

    for (int k0 = 0; k0 < FF; k0 += 32) {
        {
            const int kk = tid & 31;
            const int mbase = tid >> 5;
#pragma unroll
            for (int i = 0; i < 4; i++) {
                const int mm = mbase + i * 8;
                const int tok = s_tok[mm];
                As[kk][mm] = (tok >= 0) ? xf[(size_t)tok * FF + k0 + kk] : 0.0f;
            }
        }
        {
            const int c4 = tid & 31;
            const int rbase = tid >> 5;
#pragma unroll
            for (int p = 0; p < 4; p++) {
                const int r = rbase + p * 8;
                float4 v = *reinterpret_cast<const float4*>(&W[(size_t)(k0 + r) * DM + c4 * 4]);
                *reinterpret_cast<float4*>(&Bs[r][c4 * 4]) = v;
            }
        }
        __syncthreads();
#pragma unroll
        for (int kk = 0; kk < 32; kk++) {
            const float a0 = As[kk][ty * 4 + 0];
            const float a1 = As[kk][ty * 4 + 1];
            const float a2 = As[kk][ty * 4 + 2];
            const float a3 = As[kk][ty * 4 + 3];
#pragma unroll
            for (int j = 0; j < 4; j++) {
                const float bv = Bs[kk][tx + 32 * j];
                acc[0][j] += a0 * bv;
                acc[1][j] += a1 * bv;
                acc[2][j] += a2 * bv;
                acc[3][j] += a3 * bv;
            }
        }
        __syncthreads();
    }
#pragma unroll
    for (int i = 0; i < 4; i++) {
        const int mm = ty * 4 + i;
        const int tok = s_tok[mm];
        if (tok < 0) continue;
        const float g = s_gate[mm];
#pragma unroll
        for (int j = 0; j < 4; j++) {
            const int c = tx + 32 * j;
            atomicAdd(&g_combined[(size_t)tok * DM + c], g * (acc[i][j] + be[e * DM + c]));
        }
    }
}

// ---------------------------------------------------------------------------
// 5) finalize: out = (sum split-K general partials + bgen) + f32(bf16(combined))
//    bf16 cast is RNE, matching jnp astype(bfloat16).
// ---------------------------------------------------------------------------
__global__ void finalize_kernel(const float* __restrict__ bgen, float* __restrict__ out) {
    const int i = blockIdx.x * blockDim.x + threadIdx.x;
    if (i >= BB * DM) return;
    const int c = i & (DM - 1);
    float gen = bgen[c];
#pragma unroll
    for (int s = 0; s < GEN_SPLIT; s++)
        gen += g_gen_partial[(size_t)s * BB * DM + i];
    const float comb = g_combined[i];
    out[i] = gen + __bfloat162float(__float2bfloat16(comb));
}

// ---------------------------------------------------------------------------
extern "C" void kernel_launch(void* const* d_in, const int* in_sizes, int n_in,
                              void* d_out, int out_size) {
    const float* xf   = (const float*)d_in[0];   // cycle_curve_data [B,L,D] = [B,F]
    const float* cyc  = (const float*)d_in[1];   // cycle_numbers   [B,1]
    const float* dkp  = (const float*)d_in[2];   // DKP_embeddings  [B,768]
    const float* Wg1  = (const float*)d_in[3];   // [13569,256]
    const float* bg1  = (const float*)d_in[4];   // [256]
    const float* Wg2  = (const float*)d_in[5];   // [256,8]
    const float* bg2  = (const float*)d_in[6];   // [8]
    const float* We   = (const float*)d_in[7];   // [8,12800,128]
    const float* be   = (const float*)d_in[8];   // [8,128]
    const float* Wgen = (const float*)d_in[9];   // [12800,128]
    const float* bgen = (const float*)d_in[10];  // [128]
    float* out = (float*)d_out;

    init_zero_kernel<<<(BB * DM + 255) / 256, 256>>>();
    gate_gemm_kernel<<<dim3(BB / 32, GATE_SPLIT), 256>>>(xf, cyc, dkp, Wg1);
    gate_epilogue_kernel<<<BB / 8, 256>>>(bg1, Wg2, bg2);
    general_gemm_kernel<<<dim3(BB / 32, GEN_SPLIT), 256>>>(xf, Wgen);
    expert_gemm_kernel<<<dim3(BB / 32, NE), 256>>>(xf, We, be);
    finalize_kernel<<<(BB * DM + 255) / 256, 256>>>(bgen, out);
}

// round 3
// speedup vs baseline: 1.8626x; 1.8626x over previous
#include <cuda_runtime.h>
#include <cuda_bf16.h>

#define BB    2048
#define DM    128
#define FF    12800
#define NDLLM 768
#define NDFF  256
#define NE    8
#define NGIN  13569          // 768 + 1 + 12800

#define GSPLIT 16
#define GKSEG  864           // 54*16; 16*864 = 13824 >= 13569 (last split short)
#define NSPLIT 16
#define NKSEG  800           // 12800/16, multiple of 16
#define ESPLIT 4
#define EKSEG  3200          // 12800/4

// scratch (static device globals; no allocation allowed)
__device__ float g_gate_partial[(size_t)GSPLIT * BB * NDFF]; // 33.5 MB
__device__ float g_gen_partial[(size_t)NSPLIT * BB * DM];    // 16.8 MB
__device__ float g_combined[(size_t)BB * DM];                // 1 MB
__device__ int   g_counts[NE];
__device__ int   g_list[NE * BB];
__device__ float g_gateval[NE * BB];

// ---------------------------------------------------------------------------
// 0) zero the atomically-built accumulators
// ---------------------------------------------------------------------------
__global__ void init_zero_kernel() {
    int i = blockIdx.x * blockDim.x + threadIdx.x;
    if (i < BB * DM) g_combined[i] = 0.0f;
    if (i < NE) g_counts[i] = 0;
}

// ===========================================================================
// Shared tile-compute fragment layout (all GEMMs):
//   256 threads, CTA tile 128(M) x 128(N), BK=16, 8x8 outputs per thread.
//   warps 4x2 (m x n); lane: lm=lane>>3, ln=lane&7.
//   rows: wm*32 + lm*4 (+0..3) and +16;  cols: wn*64 + ln*4 (+0..3) and +32.
//   -> LDS.128 phases conflict-free (B: 32 distinct banks; A: broadcast).
// ===========================================================================

// ---------------------------------------------------------------------------
// 1) gate GEMM: partial[s][b][n] = sum_{k in seg s} gin[b][k] * Wg1[k][n]
//    gin = concat(DKP[768], cycle[1], xf[12800]), gathered on the fly.
//    grid: (16 m-blocks * 2 n-blocks, GSPLIT)
// ---------------------------------------------------------------------------
__global__ void __launch_bounds__(256, 2)
gate_gemm_kernel(const float* __restrict__ xf, const float* __restrict__ cyc,
                 const float* __restrict__ dkp, const float* __restrict__ Wg1) {
    __shared__ float As[2][16][132];
    __shared__ float Bs[2][16][128];
    const int bm   = (blockIdx.x & 15) * 128;
    const int nblk = blockIdx.x >> 4;             // 0..1
    const int s    = blockIdx.y;
    const int kbeg = s * GKSEG;
    const int kend = min(NGIN, kbeg + GKSEG);
    const int tid  = threadIdx.x;
    const int w = tid >> 5, lane = tid & 31;
    const int wm = w & 3, wn = w >> 2;
    const int lm = lane >> 3, ln = lane & 7;
    const int row0 = wm * 32 + lm * 4, row1 = row0 + 16;
    const int col0 = wn * 64 + ln * 4, col1 = col0 + 32;

    // loader lanes
    const int akk = tid & 15;      // k within tile
    const int am0 = tid >> 4;      // 0..15 -> m = am0 + i*16
    const int bn4 = tid & 31;      // float4 col
    const int bk0 = tid >> 5;      // 0..7 -> k = bk0 + p*8

    float  areg[8];
    float4 breg[2];
    float  acc[8][8];
#pragma unroll
    for (int i = 0; i < 8; i++)
#pragma unroll
        for (int j = 0; j < 8; j++) acc[i][j] = 0.0f;

    const int ntiles = (kend - kbeg + 15) >> 4;

#define GATE_LOAD(K0)                                                          \
    {                                                                          \
        const int k = (K0) + akk;                                              \
        _Pragma("unroll")                                                      \
        for (int i = 0; i < 8; i++) {                                          \
            const int b = bm + am0 + i * 16;                                   \
            float v = 0.0f;                                                    \
            if (k < kend) {                                                    \
                if (k < NDLLM)       v = dkp[(size_t)b * NDLLM + k];           \
                else if (k == NDLLM) v = cyc[b];                               \
                else                 v = xf[(size_t)b * FF + (k - NDLLM - 1)]; \
            }                                                                  \
            areg[i] = v;                                                       \
        }                                                                      \
        _Pragma("unroll")                                                      \
        for (int p = 0; p < 2; p++) {                                          \
            const int kb = (K0) + bk0 + p * 8;                                 \
            breg[p] = (kb < kend)                                              \
                ? *reinterpret_cast<const float4*>(                            \
                      &Wg1[(size_t)kb * NDFF + nblk * 128 + bn4 * 4])          \
                : make_float4(0.f, 0.f, 0.f, 0.f);                             \
        }                                                                      \
    }
#define TILE_STORE(BUF)                                                        \
    {                                                                          \
        _Pragma("unroll")                                                      \
        for (int i = 0; i < 8; i++) As[BUF][akk][am0 + i * 16] = areg[i];      \
        _Pragma("unroll")                                                      \
        for (int p = 0; p < 2; p++)                                            \
            *reinterpret_cast<float4*>(&Bs[BUF][bk0 + p * 8][bn4 * 4]) = breg[p]; \
    }
#define TILE_COMPUTE(BUF)                                                      \
    _Pragma("unroll")                                                          \
    for (int kk = 0; kk < 16; kk++) {                                          \
        float4 a0 = *reinterpret_cast<const float4*>(&As[BUF][kk][row0]);      \
        float4 a1 = *reinterpret_cast<const float4*>(&As[BUF][kk][row1]);      \
        float4 b0 = *reinterpret_cast<const float4*>(&Bs[BUF][kk][col0]);      \
        float4 b1 = *reinterpret_cast<const float4*>(&Bs[BUF][kk][col1]);      \
        const float av[8] = {a0.x,a0.y,a0.z,a0.w,a1.x,a1.y,a1.z,a1.w};         \
        const float bv[8] = {b0.x,b0.y,b0.z,b0.w,b1.x,b1.y,b1.z,b1.w};         \
        _Pragma("unroll")                                                      \
        for (int i = 0; i < 8; i++)                                            \
            _Pragma("unroll")                                                  \
            for (int j = 0; j < 8; j++) acc[i][j] += av[i] * bv[j];            \
    }

    GATE_LOAD(kbeg);
    TILE_STORE(0);
    __syncthreads();
    int buf = 0;
    for (int t = 0; t < ntiles; t++) {
        if (t + 1 < ntiles) GATE_LOAD(kbeg + (t + 1) * 16);
        TILE_COMPUTE(buf);
        if (t + 1 < ntiles) TILE_STORE(buf ^ 1);
        __syncthreads();
        buf ^= 1;
    }
#undef GATE_LOAD

    const size_t base = ((size_t)s * BB + bm) * NDFF + nblk * 128;
#pragma unroll
    for (int i = 0; i < 8; i++) {
        const int r = (i < 4) ? (row0 + i) : (row1 + i - 4);
        float4 v0 = make_float4(acc[i][0], acc[i][1], acc[i][2], acc[i][3]);
        float4 v1 = make_float4(acc[i][4], acc[i][5], acc[i][6], acc[i][7]);
        *reinterpret_cast<float4*>(&g_gate_partial[base + (size_t)r * NDFF + col0]) = v0;
        *reinterpret_cast<float4*>(&g_gate_partial[base + (size_t)r * NDFF + col1]) = v1;
    }
}

// ---------------------------------------------------------------------------
// 2) gate epilogue: reduce split-K partials, +bg1, gelu(tanh), @Wg2+bg2,
//    softmax over 8, top-2 (lower-index tie-break), renorm (+1e-9),
//    build per-expert dispatch lists. One warp per token.
// ---------------------------------------------------------------------------
__global__ void __launch_bounds__(256)
gate_epilogue_kernel(const float* __restrict__ bg1, const float* __restrict__ Wg2,
                     const float* __restrict__ bg2) {
    const int warp = threadIdx.x >> 5;
    const int lane = threadIdx.x & 31;
    const int t = blockIdx.x * 8 + warp;
    if (t >= BB) return;

    float h[8];
#pragma unroll
    for (int j = 0; j < 8; j++) {
        const int c = lane + 32 * j;
        float v = bg1[c];
#pragma unroll
        for (int s = 0; s < GSPLIT; s++)
            v += g_gate_partial[((size_t)s * BB + t) * NDFF + c];
        const float x = v;
        const float inner = 0.7978845608028654f * (x + 0.044715f * x * x * x);
        h[j] = 0.5f * x * (1.0f + tanhf(inner));
    }
    float le[NE];
#pragma unroll
    for (int e = 0; e < NE; e++) {
        float s = 0.0f;
#pragma unroll
        for (int j = 0; j < 8; j++)
            s += h[j] * Wg2[(size_t)(lane + 32 * j) * NE + e];
#pragma unroll
        for (int o = 16; o > 0; o >>= 1)
            s += __shfl_xor_sync(0xffffffffu, s, o);
        le[e] = s;
    }
    if (lane == 0) {
        float logits[NE];
#pragma unroll
        for (int e = 0; e < NE; e++) logits[e] = le[e] + bg2[e];
        float mx = logits[0];
#pragma unroll
        for (int e = 1; e < NE; e++) mx = fmaxf(mx, logits[e]);
        float p[NE];
        float sum = 0.0f;
#pragma unroll
        for (int e = 0; e < NE; e++) { p[e] = expf(logits[e] - mx); sum += p[e]; }
#pragma unroll
        for (int e = 0; e < NE; e++) p[e] /= sum;
        int i1 = 0;
#pragma unroll
        for (int e = 1; e < NE; e++) if (logits[e] > logits[i1]) i1 = e;
        int i2 = (i1 == 0) ? 1 : 0;
#pragma unroll
        for (int e = 0; e < NE; e++)
            if (e != i1 && logits[e] > logits[i2]) i2 = e;
        const float denom = p[i1] + p[i2] + 1e-9f;
        const float g1 = p[i1] / denom;
        const float g2 = p[i2] / denom;
        int pos1 = atomicAdd(&g_counts[i1], 1);
        g_list[i1 * BB + pos1] = t;
        g_gateval[i1 * BB + pos1] = g1;
        int pos2 = atomicAdd(&g_counts[i2], 1);
        g_list[i2 * BB + pos2] = t;
        g_gateval[i2 * BB + pos2] = g2;
    }
}

// ---------------------------------------------------------------------------
// 3) general GEMM: gen_partial[s][b][d] = sum_{k in seg s} xf[b][k]*Wgen[k][d]
//    grid: (16 m-blocks, NSPLIT)
// ---------------------------------------------------------------------------
__global__ void __launch_bounds__(256, 2)
general_gemm_kernel(const float* __restrict__ xf, const float* __restrict__ Wgen) {
    __shared__ float As[2][16][132];
    __shared__ float Bs[2][16][128];
    const int bm = blockIdx.x * 128;
    const int s = blockIdx.y;
    const int kbeg = s * NKSEG;
    const int tid = threadIdx.x;
    const int w = tid >> 5, lane = tid & 31;
    const int wm = w & 3, wn = w >> 2;
    const int lm = lane >> 3, ln = lane & 7;
    const int row0 = wm * 32 + lm * 4, row1 = row0 + 16;
    const int col0 = wn * 64 + ln * 4, col1 = col0 + 32;

    const int ak4 = tid & 3;       // float4 k-index
    const int am0 = tid >> 2;      // 0..63 -> m = am0 + i*64
    const int bn4 = tid & 31;
    const int bk0 = tid >> 5;

    float4 areg[2];
    float4 breg[2];
    float  acc[8][8];
#pragma unroll
    for (int i = 0; i < 8; i++)
#pragma unroll
        for (int j = 0; j < 8; j++) acc[i][j] = 0.0f;

#define GEN_LOAD(K0)                                                           \
    {                                                                          \
        _Pragma("unroll")                                                      \
        for (int i = 0; i < 2; i++)                                            \
            areg[i] = *reinterpret_cast<const float4*>(                        \
                &xf[(size_t)(bm + am0 + i * 64) * FF + (K0) + ak4 * 4]);       \
        _Pragma("unroll")                                                      \
        for (int p = 0; p < 2; p++)                                            \
            breg[p] = *reinterpret_cast<const float4*>(                        \
                &Wgen[(size_t)((K0) + bk0 + p * 8) * DM + bn4 * 4]);           \
    }
#define GEN_STORE(BUF)                                                         \
    {                                                                          \
        _Pragma("unroll")                                                      \
        for (int i = 0; i < 2; i++) {                                          \
            const int m = am0 + i * 64;                                        \
            As[BUF][ak4 * 4 + 0][m] = areg[i].x;                               \
            As[BUF][ak4 * 4 + 1][m] = areg[i].y;                               \
            As[BUF][ak4 * 4 + 2][m] = areg[i].z;                               \
            As[BUF][ak4 * 4 + 3][m] = areg[i].w;                               \
        }                                                                      \
        _Pragma("unroll")                                                      \
        for (int p = 0; p < 2; p++)                                            \
            *reinterpret_cast<float4*>(&Bs[BUF][bk0 + p * 8][bn4 * 4]) = breg[p]; \
    }

    GEN_LOAD(kbeg);
    GEN_STORE(0);
    __syncthreads();
    int buf = 0;
    const int ntiles = NKSEG / 16;
    for (int t = 0; t < ntiles; t++) {
        if (t + 1 < ntiles) GEN_LOAD(kbeg + (t + 1) * 16);
        TILE_COMPUTE(buf);
        if (t + 1 < ntiles) GEN_STORE(buf ^ 1);
        __syncthreads();
        buf ^= 1;
    }
#undef GEN_LOAD

#pragma unroll
    for (int i = 0; i < 8; i++) {
        const int r = bm + ((i < 4) ? (row0 + i) : (row1 + i - 4));
        float4 v0 = make_float4(acc[i][0], acc[i][1], acc[i][2], acc[i][3]);
        float4 v1 = make_float4(acc[i][4], acc[i][5], acc[i][6], acc[i][7]);
        *reinterpret_cast<float4*>(&g_gen_partial[((size_t)s * BB + r) * DM + col0]) = v0;
        *reinterpret_cast<float4*>(&g_gen_partial[((size_t)s * BB + r) * DM + col1]) = v1;
    }
}

// ---------------------------------------------------------------------------
// 4) expert GEMMs (gathered): combined[t][:] += gate*(xf[t] @ We[e] + be[e])
//    grid: (16 m-blocks, NE, ESPLIT); bias added only by split 0.
// ---------------------------------------------------------------------------
__global__ void __launch_bounds__(256, 2)
expert_gemm_kernel(const float* __restrict__ xf, const float* __restrict__ We,
                   const float* __restrict__ be) {
    __shared__ float As[2][16][132];
    __shared__ float Bs[2][16][128];
    __shared__ int   s_tok[128];
    __shared__ float s_gate[128];
    const int e = blockIdx.y;
    const int n = g_counts[e];
    const int t0 = blockIdx.x * 128;
    if (t0 >= n) return;
    const int s = blockIdx.z;
    const int kbeg = s * EKSEG;

    const int tid = threadIdx.x;
    if (tid < 128) {
        const int idx = t0 + tid;
        s_tok[tid]  = (idx < n) ? g_list[e * BB + idx] : -1;
        s_gate[tid] = (idx < n) ? g_gateval[e * BB + idx] : 0.0f;
    }
    __syncthreads();

    const int w = tid >> 5, lane = tid & 31;
    const int wm = w & 3, wn = w >> 2;
    const int lm = lane >> 3, ln = lane & 7;
    const int row0 = wm * 32 + lm * 4, row1 = row0 + 16;
    const int col0 = wn * 64 + ln * 4, col1 = col0 + 32;

    const int ak4 = tid & 3;
    const int am0 = tid >> 2;
    const int bn4 = tid & 31;
    const int bk0 = tid >> 5;
    const float* W = We + (size_t)e * FF * DM;

    float4 areg[2];
    float4 breg[2];
    float  acc[8][8];
#pragma unroll
    for (int i = 0; i < 8; i++)
#pragma unroll
        for (int j = 0; j < 8; j++) acc[i][j] = 0.0f;

#define EXP_LOAD(K0)                                                           \
    {                                                                          \
        _Pragma("unroll")                                                      \
        for (int i = 0; i < 2; i++) {                                          \
            const int tok = s_tok[am0 + i * 64];                               \
            areg[i] = (tok >= 0)                                               \
                ? *reinterpret_cast<const float4*>(                            \
                      &xf[(size_t)tok * FF + (K0) + ak4 * 4])                  \
                : make_float4(0.f, 0.f, 0.f, 0.f);                             \
        }                                                                      \
        _Pragma("unroll")                                                      \
        for (int p = 0; p < 2; p++)                                            \
            breg[p] = *reinterpret_cast<const float4*>(                        \
                &W[(size_t)((K0) + bk0 + p * 8) * DM + bn4 * 4]);              \
    }

    EXP_LOAD(kbeg);
    GEN_STORE(0);
    __syncthreads();
    int buf = 0;
    const int ntiles = EKSEG / 16;
    for (int t = 0; t < ntiles; t++) {
        if (t + 1 < ntiles) EXP_LOAD(kbeg + (t + 1) * 16);
        TILE_COMPUTE(buf);
        if (t + 1 < ntiles) GEN_STORE(buf ^ 1);
        __syncthreads();
        buf ^= 1;
    }
#undef EXP_LOAD

#pragma unroll
    for (int i = 0; i < 8; i++) {
        const int mloc = (i < 4) ? (row0 + i) : (row1 + i - 4);
        const int tok = s_tok[mloc];
        if (tok < 0) continue;
        const float g = s_gate[mloc];
#pragma unroll
        for (int j = 0; j < 8; j++) {
            const int c = (j < 4) ? (col0 + j) : (col1 + j - 4);
            float v = g * acc[i][j];
            if (s == 0) v += g * be[e * DM + c];
            atomicAdd(&g_combined[(size_t)tok * DM + c], v);
        }
    }
}

// ---------------------------------------------------------------------------
// 5) finalize: out = (sum split-K general partials + bgen) + f32(bf16(combined))
// ---------------------------------------------------------------------------
__global__ void finalize_kernel(const float* __restrict__ bgen, float* __restrict__ out) {
    const int i = blockIdx.x * blockDim.x + threadIdx.x;
    if (i >= BB * DM) return;
    const int c = i & (DM - 1);
    float gen = bgen[c];
#pragma unroll
    for (int s = 0; s < NSPLIT; s++)
        gen += g_gen_partial[(size_t)s * BB * DM + i];
    const float comb = g_combined[i];
    out[i] = gen + __bfloat162float(__float2bfloat16(comb));
}

// ---------------------------------------------------------------------------
extern "C" void kernel_launch(void* const* d_in, const int* in_sizes, int n_in,
                              void* d_out, int out_size) {
    const float* xf   = (const float*)d_in[0];   // cycle_curve_data [B,L,D] = [B,F]
    const float* cyc  = (const float*)d_in[1];   // cycle_numbers   [B,1]
    const float* dkp  = (const float*)d_in[2];   // DKP_embeddings  [B,768]
    const float* Wg1  = (const float*)d_in[3];   // [13569,256]
    const float* bg1  = (const float*)d_in[4];   // [256]
    const float* Wg2  = (const float*)d_in[5];   // [256,8]
    const float* bg2  = (const float*)d_in[6];   // [8]
    const float* We   = (const float*)d_in[7];   // [8,12800,128]
    const float* be   = (const float*)d_in[8];   // [8,128]
    const float* Wgen = (const float*)d_in[9];   // [12800,128]
    const float* bgen = (const float*)d_in[10];  // [128]
    float* out = (float*)d_out;

    init_zero_kernel<<<(BB * DM + 255) / 256, 256>>>();
    gate_gemm_kernel<<<dim3(32, GSPLIT), 256>>>(xf, cyc, dkp, Wg1);
    gate_epilogue_kernel<<<BB / 8, 256>>>(bg1, Wg2, bg2);
    general_gemm_kernel<<<dim3(16, NSPLIT), 256>>>(xf, Wgen);
    expert_gemm_kernel<<<dim3(16, NE, ESPLIT), 256>>>(xf, We, be);
    finalize_kernel<<<(BB * DM + 255) / 256, 256>>>(bgen, out);
}

// round 4
// speedup vs baseline: 1.8651x; 1.0013x over previous
#include <cuda_runtime.h>
#include <cuda_bf16.h>

#define BB    2048
#define DM    128
#define FF    12800
#define NDLLM 768
#define NDFF  256
#define NE    8
#define NGIN  13569          // 768 + 1 + 12800

#define GSPLIT 16
#define GKSEG  864           // 54*16; 16*864 = 13824 >= 13569 (last split short)
#define NSPLIT 16
#define NKSEG  800           // 12800/16, multiple of 16
#define ESPLIT 4
#define EKSEG  3200          // 12800/4

// scratch (static device globals; no allocation allowed)
__device__ float g_gate_partial[(size_t)GSPLIT * BB * NDFF]; // 33.5 MB
__device__ float g_gen_partial[(size_t)NSPLIT * BB * DM];    // 16.8 MB
__device__ float g_combined[(size_t)BB * DM];                // 1 MB
__device__ int   g_counts[NE];
__device__ int   g_list[NE * BB];
__device__ float g_gateval[NE * BB];

// ---------------------------------------------------------------------------
// 0) zero the atomically-built accumulators
// ---------------------------------------------------------------------------
__global__ void init_zero_kernel() {
    int i = blockIdx.x * blockDim.x + threadIdx.x;
    if (i < BB * DM) g_combined[i] = 0.0f;
    if (i < NE) g_counts[i] = 0;
}

// ===========================================================================
// Shared tile-compute fragment layout (all GEMMs):
//   256 threads, CTA tile 128(M) x 128(N), BK=16, 8x8 outputs per thread.
//   warps 4x2 (m x n); lane: lm=lane>>3, ln=lane&7.
//   rows: wm*32 + lm*4 (+0..3) and +16;  cols: wn*64 + ln*4 (+0..3) and +32.
//   -> LDS.128 phases conflict-free (B: 32 distinct banks; A: broadcast).
// ===========================================================================

// ---------------------------------------------------------------------------
// 1) gate GEMM: partial[s][b][n] = sum_{k in seg s} gin[b][k] * Wg1[k][n]
//    gin = concat(DKP[768], cycle[1], xf[12800]), gathered on the fly.
//    grid: (16 m-blocks * 2 n-blocks, GSPLIT)
// ---------------------------------------------------------------------------
__global__ void __launch_bounds__(256, 2)
gate_gemm_kernel(const float* __restrict__ xf, const float* __restrict__ cyc,
                 const float* __restrict__ dkp, const float* __restrict__ Wg1) {
    __shared__ float As[2][16][132];
    __shared__ float Bs[2][16][128];
    const int bm   = (blockIdx.x & 15) * 128;
    const int nblk = blockIdx.x >> 4;             // 0..1
    const int s    = blockIdx.y;
    const int kbeg = s * GKSEG;
    const int kend = min(NGIN, kbeg + GKSEG);
    const int tid  = threadIdx.x;
    const int w = tid >> 5, lane = tid & 31;
    const int wm = w & 3, wn = w >> 2;
    const int lm = lane >> 3, ln = lane & 7;
    const int row0 = wm * 32 + lm * 4, row1 = row0 + 16;
    const int col0 = wn * 64 + ln * 4, col1 = col0 + 32;

    // loader lanes
    const int akk = tid & 15;      // k within tile
    const int am0 = tid >> 4;      // 0..15 -> m = am0 + i*16
    const int bn4 = tid & 31;      // float4 col
    const int bk0 = tid >> 5;      // 0..7 -> k = bk0 + p*8

    float  areg[8];
    float4 breg[2];
    float  acc[8][8];
#pragma unroll
    for (int i = 0; i < 8; i++)
#pragma unroll
        for (int j = 0; j < 8; j++) acc[i][j] = 0.0f;

    const int ntiles = (kend - kbeg + 15) >> 4;

#define GATE_LOAD(K0)                                                          \
    {                                                                          \
        const int k = (K0) + akk;                                              \
        _Pragma("unroll")                                                      \
        for (int i = 0; i < 8; i++) {                                          \
            const int b = bm + am0 + i * 16;                                   \
            float v = 0.0f;                                                    \
            if (k < kend) {                                                    \
                if (k < NDLLM)       v = dkp[(size_t)b * NDLLM + k];           \
                else if (k == NDLLM) v = cyc[b];                               \
                else                 v = xf[(size_t)b * FF + (k - NDLLM - 1)]; \
            }                                                                  \
            areg[i] = v;                                                       \
        }                                                                      \
        _Pragma("unroll")                                                      \
        for (int p = 0; p < 2; p++) {                                          \
            const int kb = (K0) + bk0 + p * 8;                                 \
            breg[p] = (kb < kend)                                              \
                ? *reinterpret_cast<const float4*>(                            \
                      &Wg1[(size_t)kb * NDFF + nblk * 128 + bn4 * 4])          \
                : make_float4(0.f, 0.f, 0.f, 0.f);                             \
        }                                                                      \
    }
#define TILE_STORE(BUF)                                                        \
    {                                                                          \
        _Pragma("unroll")                                                      \
        for (int i = 0; i < 8; i++) As[BUF][akk][am0 + i * 16] = areg[i];      \
        _Pragma("unroll")                                                      \
        for (int p = 0; p < 2; p++)                                            \
            *reinterpret_cast<float4*>(&Bs[BUF][bk0 + p * 8][bn4 * 4]) = breg[p]; \
    }
#define TILE_COMPUTE(BUF)                                                      \
    _Pragma("unroll")                                                          \
    for (int kk = 0; kk < 16; kk++) {                                          \
        float4 a0 = *reinterpret_cast<const float4*>(&As[BUF][kk][row0]);      \
        float4 a1 = *reinterpret_cast<const float4*>(&As[BUF][kk][row1]);      \
        float4 b0 = *reinterpret_cast<const float4*>(&Bs[BUF][kk][col0]);      \
        float4 b1 = *reinterpret_cast<const float4*>(&Bs[BUF][kk][col1]);      \
        const float av[8] = {a0.x,a0.y,a0.z,a0.w,a1.x,a1.y,a1.z,a1.w};         \
        const float bv[8] = {b0.x,b0.y,b0.z,b0.w,b1.x,b1.y,b1.z,b1.w};         \
        _Pragma("unroll")                                                      \
        for (int i = 0; i < 8; i++)                                            \
            _Pragma("unroll")                                                  \
            for (int j = 0; j < 8; j++) acc[i][j] += av[i] * bv[j];            \
    }

    GATE_LOAD(kbeg);
    TILE_STORE(0);
    __syncthreads();
    int buf = 0;
    for (int t = 0; t < ntiles; t++) {
        if (t + 1 < ntiles) GATE_LOAD(kbeg + (t + 1) * 16);
        TILE_COMPUTE(buf);
        if (t + 1 < ntiles) TILE_STORE(buf ^ 1);
        __syncthreads();
        buf ^= 1;
    }
#undef GATE_LOAD

    const size_t base = ((size_t)s * BB + bm) * NDFF + nblk * 128;
#pragma unroll
    for (int i = 0; i < 8; i++) {
        const int r = (i < 4) ? (row0 + i) : (row1 + i - 4);
        float4 v0 = make_float4(acc[i][0], acc[i][1], acc[i][2], acc[i][3]);
        float4 v1 = make_float4(acc[i][4], acc[i][5], acc[i][6], acc[i][7]);
        *reinterpret_cast<float4*>(&g_gate_partial[base + (size_t)r * NDFF + col0]) = v0;
        *reinterpret_cast<float4*>(&g_gate_partial[base + (size_t)r * NDFF + col1]) = v1;
    }
}

// ---------------------------------------------------------------------------
// 2) gate epilogue: reduce split-K partials, +bg1, gelu(tanh), @Wg2+bg2,
//    softmax over 8, top-2 (lower-index tie-break), renorm (+1e-9),
//    build per-expert dispatch lists. One warp per token.
// ---------------------------------------------------------------------------
__global__ void __launch_bounds__(256)
gate_epilogue_kernel(const float* __restrict__ bg1, const float* __restrict__ Wg2,
                     const float* __restrict__ bg2) {
    const int warp = threadIdx.x >> 5;
    const int lane = threadIdx.x & 31;
    const int t = blockIdx.x * 8 + warp;
    if (t >= BB) return;

    float h[8];
#pragma unroll
    for (int j = 0; j < 8; j++) {
        const int c = lane + 32 * j;
        float v = bg1[c];
#pragma unroll
        for (int s = 0; s < GSPLIT; s++)
            v += g_gate_partial[((size_t)s * BB + t) * NDFF + c];
        const float x = v;
        const float inner = 0.7978845608028654f * (x + 0.044715f * x * x * x);
        h[j] = 0.5f * x * (1.0f + tanhf(inner));
    }
    float le[NE];
#pragma unroll
    for (int e = 0; e < NE; e++) {
        float s = 0.0f;
#pragma unroll
        for (int j = 0; j < 8; j++)
            s += h[j] * Wg2[(size_t)(lane + 32 * j) * NE + e];
#pragma unroll
        for (int o = 16; o > 0; o >>= 1)
            s += __shfl_xor_sync(0xffffffffu, s, o);
        le[e] = s;
    }
    if (lane == 0) {
        float logits[NE];
#pragma unroll
        for (int e = 0; e < NE; e++) logits[e] = le[e] + bg2[e];
        float mx = logits[0];
#pragma unroll
        for (int e = 1; e < NE; e++) mx = fmaxf(mx, logits[e]);
        float p[NE];
        float sum = 0.0f;
#pragma unroll
        for (int e = 0; e < NE; e++) { p[e] = expf(logits[e] - mx); sum += p[e]; }
#pragma unroll
        for (int e = 0; e < NE; e++) p[e] /= sum;
        int i1 = 0;
#pragma unroll
        for (int e = 1; e < NE; e++) if (logits[e] > logits[i1]) i1 = e;
        int i2 = (i1 == 0) ? 1 : 0;
#pragma unroll
        for (int e = 0; e < NE; e++)
            if (e != i1 && logits[e] > logits[i2]) i2 = e;
        const float denom = p[i1] + p[i2] + 1e-9f;
        const float g1 = p[i1] / denom;
        const float g2 = p[i2] / denom;
        int pos1 = atomicAdd(&g_counts[i1], 1);
        g_list[i1 * BB + pos1] = t;
        g_gateval[i1 * BB + pos1] = g1;
        int pos2 = atomicAdd(&g_counts[i2], 1);
        g_list[i2 * BB + pos2] = t;
        g_gateval[i2 * BB + pos2] = g2;
    }
}

// ---------------------------------------------------------------------------
// 3) general GEMM: gen_partial[s][b][d] = sum_{k in seg s} xf[b][k]*Wgen[k][d]
//    grid: (16 m-blocks, NSPLIT)
// ---------------------------------------------------------------------------
__global__ void __launch_bounds__(256, 2)
general_gemm_kernel(const float* __restrict__ xf, const float* __restrict__ Wgen) {
    __shared__ float As[2][16][132];
    __shared__ float Bs[2][16][128];
    const int bm = blockIdx.x * 128;
    const int s = blockIdx.y;
    const int kbeg = s * NKSEG;
    const int tid = threadIdx.x;
    const int w = tid >> 5, lane = tid & 31;
    const int wm = w & 3, wn = w >> 2;
    const int lm = lane >> 3, ln = lane & 7;
    const int row0 = wm * 32 + lm * 4, row1 = row0 + 16;
    const int col0 = wn * 64 + ln * 4, col1 = col0 + 32;

    const int ak4 = tid & 3;       // float4 k-index
    const int am0 = tid >> 2;      // 0..63 -> m = am0 + i*64
    const int bn4 = tid & 31;
    const int bk0 = tid >> 5;

    float4 areg[2];
    float4 breg[2];
    float  acc[8][8];
#pragma unroll
    for (int i = 0; i < 8; i++)
#pragma unroll
        for (int j = 0; j < 8; j++) acc[i][j] = 0.0f;

#define GEN_LOAD(K0)                                                           \
    {                                                                          \
        _Pragma("unroll")                                                      \
        for (int i = 0; i < 2; i++)                                            \
            areg[i] = *reinterpret_cast<const float4*>(                        \
                &xf[(size_t)(bm + am0 + i * 64) * FF + (K0) + ak4 * 4]);       \
        _Pragma("unroll")                                                      \
        for (int p = 0; p < 2; p++)                                            \
            breg[p] = *reinterpret_cast<const float4*>(                        \
                &Wgen[(size_t)((K0) + bk0 + p * 8) * DM + bn4 * 4]);           \
    }
#define GEN_STORE(BUF)                                                         \
    {                                                                          \
        _Pragma("unroll")                                                      \
        for (int i = 0; i < 2; i++) {                                          \
            const int m = am0 + i * 64;                                        \
            As[BUF][ak4 * 4 + 0][m] = areg[i].x;                               \
            As[BUF][ak4 * 4 + 1][m] = areg[i].y;                               \
            As[BUF][ak4 * 4 + 2][m] = areg[i].z;                               \
            As[BUF][ak4 * 4 + 3][m] = areg[i].w;                               \
        }                                                                      \
        _Pragma("unroll")                                                      \
        for (int p = 0; p < 2; p++)                                            \
            *reinterpret_cast<float4*>(&Bs[BUF][bk0 + p * 8][bn4 * 4]) = breg[p]; \
    }

    GEN_LOAD(kbeg);
    GEN_STORE(0);
    __syncthreads();
    int buf = 0;
    const int ntiles = NKSEG / 16;
    for (int t = 0; t < ntiles; t++) {
        if (t + 1 < ntiles) GEN_LOAD(kbeg + (t + 1) * 16);
        TILE_COMPUTE(buf);
        if (t + 1 < ntiles) GEN_STORE(buf ^ 1);
        __syncthreads();
        buf ^= 1;
    }
#undef GEN_LOAD

#pragma unroll
    for (int i = 0; i < 8; i++) {
        const int r = bm + ((i < 4) ? (row0 + i) : (row1 + i - 4));
        float4 v0 = make_float4(acc[i][0], acc[i][1], acc[i][2], acc[i][3]);
        float4 v1 = make_float4(acc[i][4], acc[i][5], acc[i][6], acc[i][7]);
        *reinterpret_cast<float4*>(&g_gen_partial[((size_t)s * BB + r) * DM + col0]) = v0;
        *reinterpret_cast<float4*>(&g_gen_partial[((size_t)s * BB + r) * DM + col1]) = v1;
    }
}

// ---------------------------------------------------------------------------
// 4) expert GEMMs (gathered): combined[t][:] += gate*(xf[t] @ We[e] + be[e])
//    grid: (16 m-blocks, NE, ESPLIT); bias added only by split 0.
// ---------------------------------------------------------------------------
__global__ void __launch_bounds__(256, 2)
expert_gemm_kernel(const float* __restrict__ xf, const float* __restrict__ We,
                   const float* __restrict__ be) {
    __shared__ float As[2][16][132];
    __shared__ float Bs[2][16][128];
    __shared__ int   s_tok[128];
    __shared__ float s_gate[128];
    const int e = blockIdx.y;
    const int n = g_counts[e];
    const int t0 = blockIdx.x * 128;
    if (t0 >= n) return;
    const int s = blockIdx.z;
    const int kbeg = s * EKSEG;

    const int tid = threadIdx.x;
    if (tid < 128) {
        const int idx = t0 + tid;
        s_tok[tid]  = (idx < n) ? g_list[e * BB + idx] : -1;
        s_gate[tid] = (idx < n) ? g_gateval[e * BB + idx] : 0.0f;
    }
    __syncthreads();

    const int w = tid >> 5, lane = tid & 31;
    const int wm = w & 3, wn = w >> 2;
    const int lm = lane >> 3, ln = lane & 7;
    const int row0 = wm * 32 + lm * 4, row1 = row0 + 16;
    const int col0 = wn * 64 + ln * 4, col1 = col0 + 32;

    const int ak4 = tid & 3;
    const int am0 = tid >> 2;
    const int bn4 = tid & 31;
    const int bk0 = tid >> 5;
    const float* W = We + (size_t)e * FF * DM;

    float4 areg[2];
    float4 breg[2];
    float  acc[8][8];
#pragma unroll
    for (int i = 0; i < 8; i++)
#pragma unroll
        for (int j = 0; j < 8; j++) acc[i][j] = 0.0f;

#define EXP_LOAD(K0)                                                           \
    {                                                                          \
        _Pragma("unroll")                                                      \
        for (int i = 0; i < 2; i++) {                                          \
            const int tok = s_tok[am0 + i * 64];                               \
            areg[i] = (tok >= 0)                                               \
                ? *reinterpret_cast<const float4*>(                            \
                      &xf[(size_t)tok * FF + (K0) + ak4 * 4])                  \
                : make_float4(0.f, 0.f, 0.f, 0.f);                             \
        }                                                                      \
        _Pragma("unroll")                                                      \
        for (int p = 0; p < 2; p++)                                            \
            breg[p] = *reinterpret_cast<const float4*>(                        \
                &W[(size_t)((K0) + bk0 + p * 8) * DM + bn4 * 4]);              \
    }

    EXP_LOAD(kbeg);
    GEN_STORE(0);
    __syncthreads();
    int buf = 0;
    const int ntiles = EKSEG / 16;
    for (int t = 0; t < ntiles; t++) {
        if (t + 1 < ntiles) EXP_LOAD(kbeg + (t + 1) * 16);
        TILE_COMPUTE(buf);
        if (t + 1 < ntiles) GEN_STORE(buf ^ 1);
        __syncthreads();
        buf ^= 1;
    }
#undef EXP_LOAD

#pragma unroll
    for (int i = 0; i < 8; i++) {
        const int mloc = (i < 4) ? (row0 + i) : (row1 + i - 4);
        const int tok = s_tok[mloc];
        if (tok < 0) continue;
        const float g = s_gate[mloc];
#pragma unroll
        for (int j = 0; j < 8; j++) {
            const int c = (j < 4) ? (col0 + j) : (col1 + j - 4);
            float v = g * acc[i][j];
            if (s == 0) v += g * be[e * DM + c];
            atomicAdd(&g_combined[(size_t)tok * DM + c], v);
        }
    }
}

// ---------------------------------------------------------------------------
// 5) finalize: out = (sum split-K general partials + bgen) + f32(bf16(combined))
// ---------------------------------------------------------------------------
__global__ void finalize_kernel(const float* __restrict__ bgen, float* __restrict__ out) {
    const int i = blockIdx.x * blockDim.x + threadIdx.x;
    if (i >= BB * DM) return;
    const int c = i & (DM - 1);
    float gen = bgen[c];
#pragma unroll
    for (int s = 0; s < NSPLIT; s++)
        gen += g_gen_partial[(size_t)s * BB * DM + i];
    const float comb = g_combined[i];
    out[i] = gen + __bfloat162float(__float2bfloat16(comb));
}

// ---------------------------------------------------------------------------
extern "C" void kernel_launch(void* const* d_in, const int* in_sizes, int n_in,
                              void* d_out, int out_size) {
    const float* xf   = (const float*)d_in[0];   // cycle_curve_data [B,L,D] = [B,F]
    const float* cyc  = (const float*)d_in[1];   // cycle_numbers   [B,1]
    const float* dkp  = (const float*)d_in[2];   // DKP_embeddings  [B,768]
    const float* Wg1  = (const float*)d_in[3];   // [13569,256]
    const float* bg1  = (const float*)d_in[4];   // [256]
    const float* Wg2  = (const float*)d_in[5];   // [256,8]
    const float* bg2  = (const float*)d_in[6];   // [8]
    const float* We   = (const float*)d_in[7];   // [8,12800,128]
    const float* be   = (const float*)d_in[8];   // [8,128]
    const float* Wgen = (const float*)d_in[9];   // [12800,128]
    const float* bgen = (const float*)d_in[10];  // [128]
    float* out = (float*)d_out;

    init_zero_kernel<<<(BB * DM + 255) / 256, 256>>>();
    gate_gemm_kernel<<<dim3(32, GSPLIT), 256>>>(xf, cyc, dkp, Wg1);
    gate_epilogue_kernel<<<BB / 8, 256>>>(bg1, Wg2, bg2);
    general_gemm_kernel<<<dim3(16, NSPLIT), 256>>>(xf, Wgen);
    expert_gemm_kernel<<<dim3(16, NE, ESPLIT), 256>>>(xf, We, be);
    finalize_kernel<<<(BB * DM + 255) / 256, 256>>>(bgen, out);
}

// round 6
// speedup vs baseline: 3.4055x; 1.8259x over previous
#include <cuda_runtime.h>
#include <cuda_bf16.h>
#include <cstdint>

#define BB    2048
#define DM    128
#define FF    12800
#define NDLLM 768
#define NDFF  256
#define NE    8
#define NGIN  13569
#define GSPLIT 16
#define GKSEG  864
#define TSPLIT 4            // tensor split-K
#define KSEG   3200         // FF/4
#define NCH    50           // KSEG/64 chunks

// ---------------- device scratch ----------------
__device__ float g_gate_partial[(size_t)GSPLIT * BB * NDFF];
__device__ __align__(16) __nv_bfloat16 g_xf_hi[(size_t)BB * FF];
__device__ __align__(16) __nv_bfloat16 g_xf_lo[(size_t)BB * FF];
__device__ __align__(16) __nv_bfloat16 g_wh[(size_t)9 * FF * DM];  // slabs 0..7 experts, 8 general
__device__ __align__(16) __nv_bfloat16 g_wl[(size_t)9 * FF * DM];
__device__ float g_exp_part[(size_t)TSPLIT * NE * BB * DM];
__device__ float g_gen_part[(size_t)TSPLIT * BB * DM];
__device__ int   g_counts[NE];
__device__ int   g_list[NE * BB];
__device__ float g_gateval[NE * BB];
__device__ int   g_entry[2 * BB];

// ---------------- PTX helpers (compute_103-safe baseline ISA only) ---------
__device__ __forceinline__ uint32_t smem_u32(const void* p) {
    uint32_t a;
    asm("{ .reg .u64 t; cvta.to.shared.u64 t, %1; cvt.u32.u64 %0, t; }" : "=r"(a) : "l"(p));
    return a;
}
#define CP16(s, g) asm volatile("cp.async.cg.shared.global [%0], [%1], 16;" :: "r"(s), "l"(g) : "memory")
#define CP_COMMIT() asm volatile("cp.async.commit_group;" ::: "memory")
#define CP_WAIT1()  asm volatile("cp.async.wait_group 1;" ::: "memory")
#define LDSM4(R, a) asm volatile("ldmatrix.sync.aligned.m8n8.x4.shared.b16 {%0,%1,%2,%3}, [%4];" \
    : "=r"((R)[0]), "=r"((R)[1]), "=r"((R)[2]), "=r"((R)[3]) : "r"(a))
#define LDSM4T(R, a) asm volatile("ldmatrix.sync.aligned.m8n8.x4.trans.shared.b16 {%0,%1,%2,%3}, [%4];" \
    : "=r"((R)[0]), "=r"((R)[1]), "=r"((R)[2]), "=r"((R)[3]) : "r"(a))
#define MMA16816(d, a, b0, b1)                                                 \
    asm volatile("mma.sync.aligned.m16n8k16.row.col.f32.bf16.bf16.f32 "        \
        "{%0,%1,%2,%3}, {%4,%5,%6,%7}, {%8,%9}, {%0,%1,%2,%3};"                \
        : "+f"((d)[0]), "+f"((d)[1]), "+f"((d)[2]), "+f"((d)[3])               \
        : "r"((a)[0]), "r"((a)[1]), "r"((a)[2]), "r"((a)[3]), "r"(b0), "r"(b1))

// ---------------------------------------------------------------------------
__global__ void init_counts_kernel() {
    if (threadIdx.x < NE) g_counts[threadIdx.x] = 0;
}

// xf -> 2-term bf16 split
__global__ void split_xf_kernel(const float* __restrict__ xf) {
    size_t g = (size_t)blockIdx.x * blockDim.x + threadIdx.x;
    if (g >= (size_t)BB * FF / 2) return;
    float2 v = reinterpret_cast<const float2*>(xf)[g];
    __nv_bfloat162 h, l;
    h.x = __float2bfloat16_rn(v.x);
    l.x = __float2bfloat16_rn(v.x - __bfloat162float(h.x));
    h.y = __float2bfloat16_rn(v.y);
    l.y = __float2bfloat16_rn(v.y - __bfloat162float(h.y));
    reinterpret_cast<__nv_bfloat162*>(g_xf_hi)[g] = h;
    reinterpret_cast<__nv_bfloat162*>(g_xf_lo)[g] = l;
}

// We[8][FF][DM] ++ Wgen[FF][DM] -> elementwise 2-term split, SAME layout
__global__ void split_w_kernel(const float* __restrict__ We, const float* __restrict__ Wgen) {
    size_t g = (size_t)blockIdx.x * blockDim.x + threadIdx.x;
    const size_t half = (size_t)9 * FF * DM / 2;
    if (g >= half) return;
    const size_t we2 = (size_t)8 * FF * DM / 2;
    float2 v = (g < we2) ? reinterpret_cast<const float2*>(We)[g]
                         : reinterpret_cast<const float2*>(Wgen)[g - we2];
    __nv_bfloat162 h, l;
    h.x = __float2bfloat16_rn(v.x);
    l.x = __float2bfloat16_rn(v.x - __bfloat162float(h.x));
    h.y = __float2bfloat16_rn(v.y);
    l.y = __float2bfloat16_rn(v.y - __bfloat162float(h.y));
    reinterpret_cast<__nv_bfloat162*>(g_wh)[g] = h;
    reinterpret_cast<__nv_bfloat162*>(g_wl)[g] = l;
}

// ---------------------------------------------------------------------------
// gate GEMM (fp32 SIMT — R2-proven, correctness-critical for top-k)
// ---------------------------------------------------------------------------
__global__ void __launch_bounds__(256, 2)
gate_gemm_kernel(const float* __restrict__ xf, const float* __restrict__ cyc,
                 const float* __restrict__ dkp, const float* __restrict__ Wg1) {
    __shared__ float As[2][16][132];
    __shared__ float Bs[2][16][128];
    const int bm   = (blockIdx.x & 15) * 128;
    const int nblk = blockIdx.x >> 4;
    const int s    = blockIdx.y;
    const int kbeg = s * GKSEG;
    const int kend = min(NGIN, kbeg + GKSEG);
    const int tid  = threadIdx.x;
    const int w = tid >> 5, lane = tid & 31;
    const int wm = w & 3, wn = w >> 2;
    const int lm = lane >> 3, ln = lane & 7;
    const int row0 = wm * 32 + lm * 4, row1 = row0 + 16;
    const int col0 = wn * 64 + ln * 4, col1 = col0 + 32;
    const int akk = tid & 15;
    const int am0 = tid >> 4;
    const int bn4 = tid & 31;
    const int bk0 = tid >> 5;

    float  areg[8];
    float4 breg[2];
    float  acc[8][8];
#pragma unroll
    for (int i = 0; i < 8; i++)
#pragma unroll
        for (int j = 0; j < 8; j++) acc[i][j] = 0.0f;

    const int ntiles = (kend - kbeg + 15) >> 4;

#define GATE_LOAD(K0)                                                          \
    {                                                                          \
        const int k = (K0) + akk;                                              \
        _Pragma("unroll")                                                      \
        for (int i = 0; i < 8; i++) {                                          \
            const int b = bm + am0 + i * 16;                                   \
            float v = 0.0f;                                                    \
            if (k < kend) {                                                    \
                if (k < NDLLM)       v = dkp[(size_t)b * NDLLM + k];           \
                else if (k == NDLLM) v = cyc[b];                               \
                else                 v = xf[(size_t)b * FF + (k - NDLLM - 1)]; \
            }                                                                  \
            areg[i] = v;                                                       \
        }                                                                      \
        _Pragma("unroll")                                                      \
        for (int p = 0; p < 2; p++) {                                          \
            const int kb = (K0) + bk0 + p * 8;                                 \
            breg[p] = (kb < kend)                                              \
                ? *reinterpret_cast<const float4*>(                            \
                      &Wg1[(size_t)kb * NDFF + nblk * 128 + bn4 * 4])          \
                : make_float4(0.f, 0.f, 0.f, 0.f);                             \
        }                                                                      \
    }
#define GATE_STORE(BUF)                                                        \
    {                                                                          \
        _Pragma("unroll")                                                      \
        for (int i = 0; i < 8; i++) As[BUF][akk][am0 + i * 16] = areg[i];      \
        _Pragma("unroll")                                                      \
        for (int p = 0; p < 2; p++)                                            \
            *reinterpret_cast<float4*>(&Bs[BUF][bk0 + p * 8][bn4 * 4]) = breg[p]; \
    }
#define TILE_COMPUTE(BUF)                                                      \
    _Pragma("unroll")                                                          \
    for (int kk = 0; kk < 16; kk++) {                                          \
        float4 a0 = *reinterpret_cast<const float4*>(&As[BUF][kk][row0]);      \
        float4 a1 = *reinterpret_cast<const float4*>(&As[BUF][kk][row1]);      \
        float4 b0 = *reinterpret_cast<const float4*>(&Bs[BUF][kk][col0]);      \
        float4 b1 = *reinterpret_cast<const float4*>(&Bs[BUF][kk][col1]);      \
        const float av[8] = {a0.x,a0.y,a0.z,a0.w,a1.x,a1.y,a1.z,a1.w};         \
        const float bv[8] = {b0.x,b0.y,b0.z,b0.w,b1.x,b1.y,b1.z,b1.w};         \
        _Pragma("unroll")                                                      \
        for (int i = 0; i < 8; i++)                                            \
            _Pragma("unroll")                                                  \
            for (int j = 0; j < 8; j++) acc[i][j] += av[i] * bv[j];            \
    }

    GATE_LOAD(kbeg);
    GATE_STORE(0);
    __syncthreads();
    int buf = 0;
    for (int t = 0; t < ntiles; t++) {
        if (t + 1 < ntiles) GATE_LOAD(kbeg + (t + 1) * 16);
        TILE_COMPUTE(buf);
        if (t + 1 < ntiles) GATE_STORE(buf ^ 1);
        __syncthreads();
        buf ^= 1;
    }
#undef GATE_LOAD

    const size_t base = ((size_t)s * BB + bm) * NDFF + nblk * 128;
#pragma unroll
    for (int i = 0; i < 8; i++) {
        const int r = (i < 4) ? (row0 + i) : (row1 + i - 4);
        float4 v0 = make_float4(acc[i][0], acc[i][1], acc[i][2], acc[i][3]);
        float4 v1 = make_float4(acc[i][4], acc[i][5], acc[i][6], acc[i][7]);
        *reinterpret_cast<float4*>(&g_gate_partial[base + (size_t)r * NDFF + col0]) = v0;
        *reinterpret_cast<float4*>(&g_gate_partial[base + (size_t)r * NDFF + col1]) = v1;
    }
}

// ---------------------------------------------------------------------------
// gate epilogue
// ---------------------------------------------------------------------------
__global__ void __launch_bounds__(256)
gate_epilogue_kernel(const float* __restrict__ bg1, const float* __restrict__ Wg2,
                     const float* __restrict__ bg2) {
    const int warp = threadIdx.x >> 5;
    const int lane = threadIdx.x & 31;
    const int t = blockIdx.x * 8 + warp;
    if (t >= BB) return;

    float h[8];
#pragma unroll
    for (int j = 0; j < 8; j++) {
        const int c = lane + 32 * j;
        float v = bg1[c];
#pragma unroll
        for (int s = 0; s < GSPLIT; s++)
            v += g_gate_partial[((size_t)s * BB + t) * NDFF + c];
        const float x = v;
        const float inner = 0.7978845608028654f * (x + 0.044715f * x * x * x);
        h[j] = 0.5f * x * (1.0f + tanhf(inner));
    }
    float le[NE];
#pragma unroll
    for (int e = 0; e < NE; e++) {
        float s = 0.0f;
#pragma unroll
        for (int j = 0; j < 8; j++)
            s += h[j] * Wg2[(size_t)(lane + 32 * j) * NE + e];
#pragma unroll
        for (int o = 16; o > 0; o >>= 1)
            s += __shfl_xor_sync(0xffffffffu, s, o);
        le[e] = s;
    }
    if (lane == 0) {
        float logits[NE];
#pragma unroll
        for (int e = 0; e < NE; e++) logits[e] = le[e] + bg2[e];
        float mx = logits[0];
#pragma unroll
        for (int e = 1; e < NE; e++) mx = fmaxf(mx, logits[e]);
        float p[NE];
        float sum = 0.0f;
#pragma unroll
        for (int e = 0; e < NE; e++) { p[e] = expf(logits[e] - mx); sum += p[e]; }
#pragma unroll
        for (int e = 0; e < NE; e++) p[e] /= sum;
        int i1 = 0;
#pragma unroll
        for (int e = 1; e < NE; e++) if (logits[e] > logits[i1]) i1 = e;
        int i2 = (i1 == 0) ? 1 : 0;
#pragma unroll
        for (int e = 0; e < NE; e++)
            if (e != i1 && logits[e] > logits[i2]) i2 = e;
        const float denom = p[i1] + p[i2] + 1e-9f;
        int pos1 = atomicAdd(&g_counts[i1], 1);
        g_list[i1 * BB + pos1] = t;
        g_gateval[i1 * BB + pos1] = p[i1] / denom;
        g_entry[2 * t + 0] = i1 * BB + pos1;
        int pos2 = atomicAdd(&g_counts[i2], 1);
        g_list[i2 * BB + pos2] = t;
        g_gateval[i2 * BB + pos2] = p[i2] / denom;
        g_entry[2 * t + 1] = i2 * BB + pos2;
    }
}

// ---------------------------------------------------------------------------
// mma.sync bf16 GEMM: experts (slab 0..7, gathered rows) + general (slab 8).
// CTA 128x128, BK=64, 2-term bf16 split (3 passes), split-K=4.
// cp.async double-buffered smem (2 x 64KB), 8 warps of 64x32 tiles.
// ---------------------------------------------------------------------------
__global__ void __launch_bounds__(256, 1)
mma_gemm_kernel() {
    __shared__ int s_tok[128];
    extern __shared__ __align__(1024) char dsm[];

    const int slab  = blockIdx.z;     // 0..7 experts, 8 general
    const int split = blockIdx.y;     // 0..3
    const int t0    = blockIdx.x * 128;
    const int tid   = threadIdx.x;
    const int wid   = tid >> 5, lane = tid & 31;
    const int wm    = wid & 1, wn = wid >> 1;

    int cnt = BB;
    if (slab < 8) {
        cnt = g_counts[slab];
        if (t0 >= cnt) return;
        if (tid < 128) {
            const int idx = t0 + tid;
            s_tok[tid] = (idx < cnt) ? g_list[slab * BB + idx] : 0;
        }
    } else {
        if (tid < 128) s_tok[tid] = t0 + tid;
    }
    __syncthreads();

    const __nv_bfloat16* Wh = g_wh + (size_t)slab * FF * DM;
    const __nv_bfloat16* Wl = g_wl + (size_t)slab * FF * DM;
    const int kbeg = split * KSEG;

#define PREFETCH(C)                                                            \
    {                                                                          \
        const int k0 = kbeg + (C) * 64;                                        \
        const uint32_t sb = smem_u32(dsm + ((C) & 1) * 65536);                 \
        _Pragma("unroll")                                                      \
        for (int i = 0; i < 4; i++) {                                          \
            const int q = tid + 256 * i;                                       \
            const int m = q >> 3, kb16 = q & 7;                                \
            const uint32_t offa = (uint32_t)(m * 128 + kb16 * 16);             \
            const uint32_t swa = offa ^ ((offa >> 3) & 0x70);                  \
            const size_t ga = (size_t)s_tok[m] * FF + k0 + kb16 * 8;           \
            CP16(sb + swa, g_xf_hi + ga);                                      \
            CP16(sb + 16384 + swa, g_xf_lo + ga);                              \
            const int kk = q >> 4, nb16 = q & 15;                              \
            const uint32_t offb = (uint32_t)(kk * 256 + nb16 * 16);            \
            const uint32_t swb = offb ^ ((offb >> 4) & 0x70);                  \
            const size_t gb = (size_t)(k0 + kk) * DM + nb16 * 8;               \
            CP16(sb + 32768 + swb, Wh + gb);                                   \
            CP16(sb + 49152 + swb, Wl + gb);                                   \
        }                                                                      \
    }

    float acc[4][4][4];
#pragma unroll
    for (int a = 0; a < 4; a++)
#pragma unroll
        for (int b = 0; b < 4; b++)
#pragma unroll
            for (int c = 0; c < 4; c++) acc[a][b][c] = 0.0f;

    PREFETCH(0);
    CP_COMMIT();

    for (int c = 0; c < NCH; ++c) {
        if (c + 1 < NCH) PREFETCH(c + 1);
        CP_COMMIT();
        CP_WAIT1();
        __syncthreads();

        const uint32_t sA  = smem_u32(dsm + (c & 1) * 65536);
        const uint32_t sAl = sA + 16384, sBh = sA + 32768, sBl = sA + 49152;
#pragma unroll
        for (int ks = 0; ks < 4; ++ks) {
            uint32_t ah[4][4], al[4][4], bh[2][4], bl[2][4];
            const int arow = wm * 64 + (lane & 15);
            const int akb  = ks * 32 + ((lane >> 4) & 1) * 16;
#pragma unroll
            for (int mi = 0; mi < 4; ++mi) {
                const uint32_t off = (uint32_t)((arow + mi * 16) * 128 + akb);
                const uint32_t sw = off ^ ((off >> 3) & 0x70);
                LDSM4(ah[mi], sA + sw);
                LDSM4(al[mi], sAl + sw);
            }
            const int brow = ks * 16 + (lane & 15);
#pragma unroll
            for (int nj = 0; nj < 2; ++nj) {
                const uint32_t off = (uint32_t)(brow * 256 +
                    (wn * 32 + nj * 16) * 2 + ((lane >> 4) & 1) * 16);
                const uint32_t sw = off ^ ((off >> 4) & 0x70);
                LDSM4T(bh[nj], sBh + sw);
                LDSM4T(bl[nj], sBl + sw);
            }
#pragma unroll
            for (int mi = 0; mi < 4; ++mi)
#pragma unroll
                for (int nj = 0; nj < 2; ++nj)
#pragma unroll
                    for (int hh = 0; hh < 2; ++hh) {
                        const int nf = nj * 2 + hh;
                        MMA16816(acc[mi][nf], ah[mi], bh[nj][hh * 2], bh[nj][hh * 2 + 1]);
                        MMA16816(acc[mi][nf], ah[mi], bl[nj][hh * 2], bl[nj][hh * 2 + 1]);
                        MMA16816(acc[mi][nf], al[mi], bh[nj][hh * 2], bh[nj][hh * 2 + 1]);
                    }
        }
        __syncthreads();
    }
#undef PREFETCH

    // epilogue: write fp32 partials
    float* optr;
    size_t obase;
    if (slab < 8) {
        optr = g_exp_part;
        obase = ((size_t)split * (NE * BB) + (size_t)slab * BB + t0) * DM;
    } else {
        optr = g_gen_part;
        obase = ((size_t)split * BB + t0) * DM;
    }
#pragma unroll
    for (int mi = 0; mi < 4; ++mi) {
        const int r0 = wm * 64 + mi * 16 + (lane >> 2);
        const int r1 = r0 + 8;
        const bool v0 = (t0 + r0) < cnt, v1 = (t0 + r1) < cnt;
#pragma unroll
        for (int nf = 0; nf < 4; ++nf) {
            const int cc = wn * 32 + nf * 8 + (lane & 3) * 2;
            if (v0) *reinterpret_cast<float2*>(&optr[obase + (size_t)r0 * DM + cc]) =
                make_float2(acc[mi][nf][0], acc[mi][nf][1]);
            if (v1) *reinterpret_cast<float2*>(&optr[obase + (size_t)r1 * DM + cc]) =
                make_float2(acc[mi][nf][2], acc[mi][nf][3]);
        }
    }
}

// ---------------------------------------------------------------------------
// finalize: deterministic combine. comb = sum_{2 entries} gate*(be + 4 splits);
// out = (bgen + 4 gen splits) + f32(bf16(comb)).
// ---------------------------------------------------------------------------
__global__ void finalize_kernel(const float* __restrict__ be, const float* __restrict__ bgen,
                                float* __restrict__ out) {
    const int i = blockIdx.x * blockDim.x + threadIdx.x;
    if (i >= BB * DM) return;
    const int t = i >> 7, c = i & 127;
    float comb = 0.0f;
#pragma unroll
    for (int j = 0; j < 2; ++j) {
        const int ent = g_entry[2 * t + j];
        const int e = ent >> 11;
        float dot = be[e * DM + c];
#pragma unroll
        for (int sp = 0; sp < TSPLIT; ++sp)
            dot += g_exp_part[((size_t)sp * (NE * BB) + ent) * DM + c];
        comb += g_gateval[ent] * dot;
    }
    float gen = bgen[c];
#pragma unroll
    for (int sp = 0; sp < TSPLIT; ++sp)
        gen += g_gen_part[((size_t)sp * BB + t) * DM + c];
    out[i] = gen + __bfloat162float(__float2bfloat16(comb));
}

// ---------------------------------------------------------------------------
extern "C" void kernel_launch(void* const* d_in, const int* in_sizes, int n_in,
                              void* d_out, int out_size) {
    const float* xf   = (const float*)d_in[0];
    const float* cyc  = (const float*)d_in[1];
    const float* dkp  = (const float*)d_in[2];
    const float* Wg1  = (const float*)d_in[3];
    const float* bg1  = (const float*)d_in[4];
    const float* Wg2  = (const float*)d_in[5];
    const float* bg2  = (const float*)d_in[6];
    const float* We   = (const float*)d_in[7];
    const float* be   = (const float*)d_in[8];
    const float* Wgen = (const float*)d_in[9];
    const float* bgen = (const float*)d_in[10];
    float* out = (float*)d_out;

    cudaFuncSetAttribute(mma_gemm_kernel,
                         cudaFuncAttributeMaxDynamicSharedMemorySize, 131072);

    init_counts_kernel<<<1, 32>>>();
    split_xf_kernel<<<(int)(((size_t)BB * FF / 2 + 255) / 256), 256>>>(xf);
    split_w_kernel<<<(int)(((size_t)9 * FF * DM / 2 + 255) / 256), 256>>>(We, Wgen);
    gate_gemm_kernel<<<dim3(32, GSPLIT), 256>>>(xf, cyc, dkp, Wg1);
    gate_epilogue_kernel<<<BB / 8, 256>>>(bg1, Wg2, bg2);
    mma_gemm_kernel<<<dim3(16, TSPLIT, 9), 256, 131072>>>();
    finalize_kernel<<<(BB * DM + 255) / 256, 256>>>(be, bgen, out);
}